// round 6
// baseline (speedup 1.0000x reference)
#include <cuda_runtime.h>
#include <math.h>

// ---------------------------------------------------------------------------
// ContinuousFilterConv
//   df[e,g]   = exp(-10 (d_e - c_g)^2), c_g = 30*g/49
//   h[e,:]    = silu(df @ W1 + b1)                       [E,128]
//   t[e,:]    = node_features[src[e]] @ Wt               [E,128]
//   filtered[e,i] = sum_{u,j} h'[e,u] t[e,j] W2'[u, i*128+j]   (* mask[e])
//       where h' has an extra u=128 row == 1 and W2' row 128 == b2
//   messages  = scatter_add over dst;  out = silu(messages)
//
// Main GEMM: C[E,128] = A[E, 129*128] * B, A generated on the fly from h,t.
// SIMT fp32 using Blackwell packed fma.rn.f32x2 (2 FMAs / instr).
// ---------------------------------------------------------------------------

#define N_NODES 20000
#define N_EDGES 8192
#define UNITS   128
#define NGAUSS  50
#define KSPLITS 7
#define ROWP    132           // padded SMEM row (floats)

// scratch (static device memory only — no allocation allowed)
__device__ float g_hT[129 * N_EDGES];   // hT[u][e], row 128 == 1.0
__device__ float g_tT[UNITS * N_EDGES]; // tT[u'][e]
__device__ float g_msg[N_NODES * UNITS];

__device__ __forceinline__ float silu_f(float x) {
    return x / (1.0f + expf(-x));
}

__device__ __forceinline__ unsigned long long pack2dup(float x) {
    unsigned long long r;
    asm("mov.b64 %0, {%1, %1};" : "=l"(r) : "f"(x));
    return r;
}
__device__ __forceinline__ void fma2(unsigned long long& d,
                                     unsigned long long a,
                                     unsigned long long b) {
    asm("fma.rn.f32x2 %0, %1, %2, %0;" : "+l"(d) : "l"(a), "l"(b));
}
__device__ __forceinline__ float2 unpack2(unsigned long long v) {
    float2 f;
    asm("mov.b64 {%0, %1}, %2;" : "=f"(f.x), "=f"(f.y) : "l"(v));
    return f;
}

// ---------------------------------------------------------------------------
// kernel 0: zero the message accumulator (d_out is poisoned; g_msg persists)
// ---------------------------------------------------------------------------
__global__ void zero_msg_kernel() {
    int i = blockIdx.x * blockDim.x + threadIdx.x; // grid sized exactly
    g_msg[i] = 0.0f;
}

// ---------------------------------------------------------------------------
// kernel 1: per-edge h (gaussian basis -> dense -> silu) and t (gather @ Wt)
// 64 edges per block, 256 threads.
// ---------------------------------------------------------------------------
__global__ __launch_bounds__(256) void prep_kernel(
    const float* __restrict__ nf,   // [N_NODES,128]
    const int*   __restrict__ eidx, // [2, E]
    const float* __restrict__ dist, // [E]
    const float* __restrict__ W1,   // [50,128]
    const float* __restrict__ b1,   // [128]
    const float* __restrict__ Wt)   // [128,128]
{
    __shared__ float df_s[64 * 51];
    __shared__ float X_s[64 * 129];
    const int tid = threadIdx.x;
    const int e0  = blockIdx.x * 64;

    // gaussian basis
    for (int idx = tid; idx < 64 * NGAUSS; idx += 256) {
        int e = idx & 63, g = idx >> 6;
        float d = dist[e0 + e];
        float c = (30.0f / 49.0f) * (float)g;
        float x = d - c;
        df_s[e * 51 + g] = expf(-10.0f * x * x);
    }
    // gather source node features
    for (int idx = tid; idx < 64 * UNITS; idx += 256) {
        int e = idx >> 7, j = idx & 127;
        int s = eidx[e0 + e]; // row 0 = src
        X_s[e * 129 + j] = nf[(long long)s * UNITS + j];
    }
    __syncthreads();

    // h[e,u] = silu(df . W1[:,u] + b1[u]); store transposed hT[u][e]
    for (int o = tid; o < 64 * UNITS; o += 256) {
        int u = o >> 6, e = o & 63;
        float acc = b1[u];
        const float* dfr = df_s + e * 51;
#pragma unroll
        for (int g = 0; g < NGAUSS; ++g) acc += dfr[g] * W1[g * UNITS + u];
        g_hT[u * N_EDGES + e0 + e] = silu_f(acc);
    }
    // ones row (bias folding)
    for (int idx = tid; idx < 64; idx += 256)
        g_hT[128 * N_EDGES + e0 + idx] = 1.0f;

    // t[e,u'] = X . Wt[:,u']; store transposed tT[u'][e]
    for (int o = tid; o < 64 * UNITS; o += 256) {
        int u = o >> 6, e = o & 63;
        float acc = 0.0f;
        const float* xr = X_s + e * 129;
#pragma unroll
        for (int j = 0; j < UNITS; ++j) acc += xr[j] * Wt[j * UNITS + u];
        g_tT[u * N_EDGES + e0 + e] = acc;
    }
}

// ---------------------------------------------------------------------------
// kernel 2: main contraction. Block tile: 128 edges x 128 i, K split over u.
// Per u: stage W2 row u as Bs[j][i] (transposed) in SMEM, rank-1-update
// A[e,(u,j)] = h[e,u]*t[e,j] against it. Epilogue: mask + atomicAdd scatter.
// ---------------------------------------------------------------------------
__global__ __launch_bounds__(256) void conv_kernel(
    const float* __restrict__ W2,   // [128, 16384]
    const float* __restrict__ b2,   // [16384]
    const int*   __restrict__ eidx, // [2, E]
    const float* __restrict__ dist) // [E]
{
    extern __shared__ float smem[];
    float* Ts = smem;                  // [128][ROWP]  t tile (j-major)
    float* Bs = Ts + 128 * ROWP;       // [128][ROWP]  W2 row u, transposed [j][i]
    float* Hs = Bs + 128 * ROWP;       // [<=19][ROWP] h slice (u-major)

    const int tid = threadIdx.x;
    const int e0  = blockIdx.x * 128;
    const int s   = blockIdx.y;
    const int ub  = (129 * s) / KSPLITS;
    const int ue  = (129 * (s + 1)) / KSPLITS;

    for (int idx = tid; idx < 128 * 128; idx += 256) {
        int j = idx >> 7, e = idx & 127;
        Ts[j * ROWP + e] = g_tT[j * N_EDGES + e0 + e];
    }
    for (int idx = tid; idx < (ue - ub) * 128; idx += 256) {
        int ul = idx >> 7, e = idx & 127;
        Hs[ul * ROWP + e] = g_hT[(ub + ul) * N_EDGES + e0 + e];
    }

    const int tx = tid & 15, ty = tid >> 4;
    const int i0 = tx * 4;        // i columns: i0..i0+3, i0+64..i0+67
    const int el0 = ty * 4;       // edges: el0..el0+3, el0+64..el0+67

    unsigned long long acc2[8][4];
#pragma unroll
    for (int m = 0; m < 8; ++m)
#pragma unroll
        for (int q = 0; q < 4; ++q) acc2[m][q] = 0ULL;

    for (int u = ub; u < ue; ++u) {
        const float* srcp = (u < 128) ? (W2 + (long long)u * (UNITS * UNITS)) : b2;
        __syncthreads();   // previous-iteration compute done before Bs overwrite
                           // (also orders Ts/Hs fills before first compute)
        // load W2 row u (i-major in gmem) into Bs[j][i]
#pragma unroll
        for (int p = 0; p < 16; ++p) {
            int i  = (tid >> 5) + p * 8;
            int j4 = (tid & 31) * 4;
            float4 v = *(const float4*)(srcp + i * 128 + j4);
            Bs[(j4 + 0) * ROWP + i] = v.x;
            Bs[(j4 + 1) * ROWP + i] = v.y;
            Bs[(j4 + 2) * ROWP + i] = v.z;
            Bs[(j4 + 3) * ROWP + i] = v.w;
        }
        __syncthreads();

        float hu[8];
        {
            const float* hr = Hs + (u - ub) * ROWP + el0;
            float4 a = *(const float4*)hr;
            float4 b = *(const float4*)(hr + 64);
            hu[0] = a.x; hu[1] = a.y; hu[2] = a.z; hu[3] = a.w;
            hu[4] = b.x; hu[5] = b.y; hu[6] = b.z; hu[7] = b.w;
        }

#pragma unroll 4
        for (int j = 0; j < 128; ++j) {
            const float* tr = Ts + j * ROWP + el0;
            float4 ta = *(const float4*)tr;
            float4 tb = *(const float4*)(tr + 64);
            const float* br = Bs + j * ROWP + i0;
            unsigned long long b0 = ((const unsigned long long*)br)[0];
            unsigned long long b1v = ((const unsigned long long*)br)[1];
            unsigned long long b2v = ((const unsigned long long*)(br + 64))[0];
            unsigned long long b3v = ((const unsigned long long*)(br + 64))[1];

            float am[8] = {hu[0] * ta.x, hu[1] * ta.y, hu[2] * ta.z, hu[3] * ta.w,
                           hu[4] * tb.x, hu[5] * tb.y, hu[6] * tb.z, hu[7] * tb.w};
#pragma unroll
            for (int m = 0; m < 8; ++m) {
                unsigned long long a2 = pack2dup(am[m]);
                fma2(acc2[m][0], a2, b0);
                fma2(acc2[m][1], a2, b1v);
                fma2(acc2[m][2], a2, b2v);
                fma2(acc2[m][3], a2, b3v);
            }
        }
    }

    // epilogue: cutoff mask + scatter-add to destination nodes
#pragma unroll
    for (int m = 0; m < 8; ++m) {
        int e = e0 + el0 + ((m < 4) ? m : (64 + m - 4));
        float d = dist[e];
        if (d <= 8.0f) {
            int dn = eidx[N_EDGES + e]; // row 1 = dst
            float* row = g_msg + (long long)dn * UNITS;
#pragma unroll
            for (int q = 0; q < 4; ++q) {
                float2 v = unpack2(acc2[m][q]);
                int ib = i0 + ((q < 2) ? (q * 2) : (64 + (q - 2) * 2));
                atomicAdd(row + ib, v.x);
                atomicAdd(row + ib + 1, v.y);
            }
        }
    }
}

// ---------------------------------------------------------------------------
// kernel 3: out = silu(messages)
// ---------------------------------------------------------------------------
__global__ void out_kernel(float* __restrict__ out) {
    int i = blockIdx.x * blockDim.x + threadIdx.x;
    if (i < N_NODES * UNITS) {
        float x = g_msg[i];
        out[i] = x / (1.0f + expf(-x));
    }
}

// ---------------------------------------------------------------------------
extern "C" void kernel_launch(void* const* d_in, const int* in_sizes, int n_in,
                              void* d_out, int out_size) {
    const float* nf   = (const float*)d_in[0]; // node_features [20000,128]
    const int*   eidx = (const int*)  d_in[1]; // edge_indices [2,8192]
    const float* dist = (const float*)d_in[2]; // distances [8192]
    const float* W1   = (const float*)d_in[3]; // [50,128]
    const float* b1   = (const float*)d_in[4]; // [128]
    const float* W2   = (const float*)d_in[5]; // [128,16384]
    const float* b2   = (const float*)d_in[6]; // [16384]
    const float* Wt   = (const float*)d_in[7]; // [128,128]
    float* out = (float*)d_out;

    const int SMEM_BYTES = (128 * ROWP + 128 * ROWP + 19 * ROWP) * 4; // 145200
    cudaFuncSetAttribute(conv_kernel,
                         cudaFuncAttributeMaxDynamicSharedMemorySize, SMEM_BYTES);

    zero_msg_kernel<<<(N_NODES * UNITS) / 1024, 1024>>>();
    prep_kernel<<<N_EDGES / 64, 256>>>(nf, eidx, dist, W1, b1, Wt);
    conv_kernel<<<dim3(N_EDGES / 128, KSPLITS), 256, SMEM_BYTES>>>(W2, b2, eidx, dist);
    out_kernel<<<(N_NODES * UNITS + 255) / 256, 256>>>(out);
}

// round 8
// speedup vs baseline: 3.5698x; 3.5698x over previous
#include <cuda_runtime.h>
#include <cuda_bf16.h>
#include <math.h>
#include <stdint.h>

// ---------------------------------------------------------------------------
// ContinuousFilterConv via mma.sync split-bf16 GEMM (arch-agnostic PTX only:
// the harness compiles at baseline sm_100, so no tcgen05/TMEM).
//
//   C[e,i] = sum_{u,j} (h[e,u]*t[e,j]) * W2'[u, i*128+j]  (u=128 row: h=1 -> b2)
//   split x = x_hi + x_lo (bf16 each); C = AhBh + AhBl + AlBh (AlBl ~2^-18)
//   A_u generated per-u in SMEM; B_u pre-split/padded in gmem, cp.async'd.
//   Accumulate fp32 in registers across all u; one masked atomic epilogue.
// ---------------------------------------------------------------------------

#define N_NODES 20000
#define N_EDGES 8192
#define UNITS   128
#define NGAUSS  50
#define LDA     136          // padded row length in bf16 elements (272 bytes)

// ---- gmem scratch (static only) ----
__device__ float g_hT[129 * N_EDGES];   // hT[u][e], row 128 == 1.0
__device__ float g_t [N_EDGES * UNITS]; // t[e][j]
__device__ uint4 g_B4[129 * 4352];      // per u: 2176 uint4 hi, then 2176 lo (rows padded to LDA)
__device__ float g_msg[N_NODES * UNITS];

// ---- helpers ----
__device__ __forceinline__ uint32_t smem_u32(const void* p) {
    uint32_t a;
    asm("{ .reg .u64 t; cvta.to.shared.u64 t, %1; cvt.u32.u64 %0, t; }" : "=r"(a) : "l"(p));
    return a;
}
__device__ __forceinline__ void cp16(uint32_t saddr, const void* g) {
    asm volatile("cp.async.cg.shared.global [%0], [%1], 16;" :: "r"(saddr), "l"(g) : "memory");
}
#define CP_COMMIT() asm volatile("cp.async.commit_group;" ::: "memory")
#define CP_WAIT0()  asm volatile("cp.async.wait_group 0;" ::: "memory")

#define LDSM4(R, A) \
    asm volatile("ldmatrix.sync.aligned.m8n8.x4.shared.b16 {%0,%1,%2,%3}, [%4];" \
        : "=r"((R)[0]), "=r"((R)[1]), "=r"((R)[2]), "=r"((R)[3]) : "r"(A))

#define MMA(C, A, B0, B1) \
    asm volatile("mma.sync.aligned.m16n8k16.row.col.f32.bf16.bf16.f32 " \
        "{%0,%1,%2,%3},{%4,%5,%6,%7},{%8,%9},{%0,%1,%2,%3};" \
        : "+f"((C)[0]), "+f"((C)[1]), "+f"((C)[2]), "+f"((C)[3]) \
        : "r"((A)[0]), "r"((A)[1]), "r"((A)[2]), "r"((A)[3]), "r"(B0), "r"(B1))

__device__ __forceinline__ void split2(float x0, float x1, uint32_t& hi, uint32_t& lo) {
    __nv_bfloat16 h0 = __float2bfloat16(x0), h1 = __float2bfloat16(x1);
    float r0 = x0 - __bfloat162float(h0), r1 = x1 - __bfloat162float(h1);
    __nv_bfloat16 l0 = __float2bfloat16(r0), l1 = __float2bfloat16(r1);
    hi = (uint32_t)__bfloat16_as_ushort(h0) | ((uint32_t)__bfloat16_as_ushort(h1) << 16);
    lo = (uint32_t)__bfloat16_as_ushort(l0) | ((uint32_t)__bfloat16_as_ushort(l1) << 16);
}
__device__ __forceinline__ float silu_f(float x) { return x / (1.0f + expf(-x)); }

// ---------------------------------------------------------------------------
// kernel 0: zero message accumulator
// ---------------------------------------------------------------------------
__global__ void zero_msg_kernel() {
    g_msg[blockIdx.x * blockDim.x + threadIdx.x] = 0.0f;  // grid sized exactly
}

// ---------------------------------------------------------------------------
// kernel 1: W2/b2 -> bf16 hi/lo slabs, padded rows (LDA), hi then lo per u.
// one thread = 8 consecutive j of one (u, i)
// ---------------------------------------------------------------------------
__global__ __launch_bounds__(256) void w2_convert_kernel(
    const float* __restrict__ W2, const float* __restrict__ b2)
{
    int g  = blockIdx.x * 256 + threadIdx.x;       // < 129*2048
    int u  = g >> 11, rem = g & 2047;
    int i  = rem >> 4, jq = rem & 15;
    const float* row = (u < 128) ? (W2 + (long long)u * 16384) : b2;
    float4 a = *(const float4*)(row + i * 128 + jq * 8);
    float4 b = *(const float4*)(row + i * 128 + jq * 8 + 4);
    float x[8] = {a.x, a.y, a.z, a.w, b.x, b.y, b.z, b.w};
    uint32_t hi[4], lo[4];
#pragma unroll
    for (int k = 0; k < 4; ++k) split2(x[2 * k], x[2 * k + 1], hi[k], lo[k]);
    int base = u * 4352 + i * 17 + jq;             // uint4 units (17 per padded row)
    g_B4[base]        = make_uint4(hi[0], hi[1], hi[2], hi[3]);
    g_B4[base + 2176] = make_uint4(lo[0], lo[1], lo[2], lo[3]);
}

// ---------------------------------------------------------------------------
// kernel 2: per-edge h (gaussian -> dense -> silu, transposed) + t (gather @ Wt)
// 64 edges / block, 256 threads; W1, b1, Wt staged in SMEM.
// ---------------------------------------------------------------------------
__global__ __launch_bounds__(256) void prep_kernel(
    const float* __restrict__ nf, const int* __restrict__ eidx,
    const float* __restrict__ dist, const float* __restrict__ W1,
    const float* __restrict__ b1, const float* __restrict__ Wt)
{
    extern __shared__ float sm[];
    float* Wt_s = sm;                       // 16384
    float* W1_s = Wt_s + 16384;             // 6400
    float* b1_s = W1_s + 6400;              // 128
    float* X_s  = b1_s + 128;               // 64*129
    float* df_s = X_s + 64 * 129;           // 64*51
    const int tid = threadIdx.x;
    const int e0  = blockIdx.x * 64;

    for (int idx = tid; idx < 16384; idx += 256) Wt_s[idx] = Wt[idx];
    for (int idx = tid; idx < NGAUSS * UNITS; idx += 256) W1_s[idx] = W1[idx];
    if (tid < 128) b1_s[tid] = b1[tid];
    for (int idx = tid; idx < 64 * NGAUSS; idx += 256) {
        int e = idx & 63, g = idx >> 6;
        float d = dist[e0 + e];
        float c = (30.0f / 49.0f) * (float)g;
        float x = d - c;
        df_s[e * 51 + g] = expf(-10.0f * x * x);
    }
    for (int idx = tid; idx < 64 * UNITS; idx += 256) {
        int e = idx >> 7, j = idx & 127;
        int s = eidx[e0 + e];
        X_s[e * 129 + j] = nf[(long long)s * UNITS + j];
    }
    __syncthreads();

    // hT[u][e] = silu(df . W1[:,u] + b1[u])
    for (int o = tid; o < 64 * UNITS; o += 256) {
        int u = o >> 6, e = o & 63;
        float acc = b1_s[u];
        const float* dfr = df_s + e * 51;
#pragma unroll
        for (int g = 0; g < NGAUSS; ++g) acc += dfr[g] * W1_s[g * UNITS + u];
        g_hT[u * N_EDGES + e0 + e] = silu_f(acc);
    }
    for (int idx = tid; idx < 64; idx += 256)
        g_hT[128 * N_EDGES + e0 + idx] = 1.0f;

    // t[e][u] = X . Wt[:,u]
    for (int o = tid; o < 64 * UNITS; o += 256) {
        int e = o >> 7, u = o & 127;
        float acc = 0.0f;
        const float* xr = X_s + e * 129;
#pragma unroll
        for (int j = 0; j < UNITS; ++j) acc += xr[j] * Wt_s[j * UNITS + u];
        g_t[(long long)(e0 + e) * UNITS + u] = acc;
    }
}

// ---------------------------------------------------------------------------
// kernel 3: main GEMM. CTA = 128 edges x 128 i; grid.y splits u.
// 8 warps in 2(M) x 4(N): each warp 64M x 32N, reg accum 4x4 m16n8 tiles.
// ---------------------------------------------------------------------------
#define TS_OFF 0
#define AH_OFF 67584
#define AL_OFF 102400
#define BH_OFF 137216
#define BL_OFF 172032
#define CONV_SMEM 206848

__global__ __launch_bounds__(256, 1) void conv_kernel(
    const int* __restrict__ eidx, const float* __restrict__ dist)
{
    extern __shared__ char smem[];
    float* Ts = (float*)smem;                 // [128][132] fp32
    const uint32_t sb = smem_u32(smem);
    const int tid = threadIdx.x, l = tid & 31, wid = tid >> 5;
    const int e0 = blockIdx.x * 128;
    const int ub = blockIdx.y ? 65 : 0;
    const int ue = blockIdx.y ? 129 : 65;

    // stage t tile
    for (int idx = tid; idx < 128 * 128; idx += 256) {
        int e = idx >> 7, j = idx & 127;
        Ts[e * 132 + j] = g_t[(long long)(e0 + e) * UNITS + j];
    }

    // per-warp fragment base offsets (byte offsets within A/B tiles)
    const int m0w = (wid & 1) * 64;
    const int n0w = (wid >> 1) * 32;
    const uint32_t aOff = (uint32_t)(m0w + (l & 7) + ((l >> 3) & 1) * 8) * (LDA * 2)
                        + (uint32_t)(l >> 4) * 16;
    const uint32_t bOff = (uint32_t)(n0w + (l & 7) + ((l >> 4) & 1) * 8) * (LDA * 2)
                        + (uint32_t)((l >> 3) & 1) * 16;

    float acc[4][4][4];
#pragma unroll
    for (int mt = 0; mt < 4; ++mt)
#pragma unroll
        for (int nt = 0; nt < 4; ++nt)
#pragma unroll
            for (int q = 0; q < 4; ++q) acc[mt][nt][q] = 0.0f;

    // A-gen mapping: thread -> (edge eA, j-half jh)
    const int eA = tid >> 1;
    const int jh = (tid & 1) * 64;
    const float* trow = Ts + eA * 132 + jh;
    const uint32_t aGen = (uint32_t)eA * (LDA * 2) + (uint32_t)jh * 2;  // bytes

    __syncthreads();  // Ts ready

    for (int u = ub; u < ue; ++u) {
        // prefetch B slab (hi+lo, 4352 uint4) — overlaps with A-gen
        const uint4* gb = g_B4 + u * 4352;
#pragma unroll
        for (int k2 = 0; k2 < 17; ++k2)
            cp16(sb + BH_OFF + (uint32_t)(tid + k2 * 256) * 16, gb + tid + k2 * 256);
        CP_COMMIT();

        // generate A_u = h[e,u]*t[e,:] hi/lo into padded SMEM rows
        float hv = g_hT[u * N_EDGES + e0 + eA];
#pragma unroll
        for (int gq = 0; gq < 8; ++gq) {
            float4 a4 = *(const float4*)(trow + gq * 8);
            float4 b4 = *(const float4*)(trow + gq * 8 + 4);
            uint32_t hi[4], lo[4];
            split2(hv * a4.x, hv * a4.y, hi[0], lo[0]);
            split2(hv * a4.z, hv * a4.w, hi[1], lo[1]);
            split2(hv * b4.x, hv * b4.y, hi[2], lo[2]);
            split2(hv * b4.z, hv * b4.w, hi[3], lo[3]);
            uint32_t off = aGen + (uint32_t)gq * 16;
            *(uint4*)(smem + AH_OFF + off) = make_uint4(hi[0], hi[1], hi[2], hi[3]);
            *(uint4*)(smem + AL_OFF + off) = make_uint4(lo[0], lo[1], lo[2], lo[3]);
        }
        CP_WAIT0();
        __syncthreads();

        // K loop: 8 chunks of 16; fragments shared across the 3 passes
#pragma unroll
        for (int kc = 0; kc < 8; ++kc) {
            uint32_t ah[4][4], al[4][4], bh[2][4], bl[2][4];
#pragma unroll
            for (int mt = 0; mt < 4; ++mt) {
                uint32_t ad = sb + aOff + (uint32_t)mt * 16 * (LDA * 2) + (uint32_t)kc * 32;
                LDSM4(ah[mt], ad + AH_OFF);
                LDSM4(al[mt], ad + AL_OFF);
            }
#pragma unroll
            for (int bt = 0; bt < 2; ++bt) {
                uint32_t bd = sb + bOff + (uint32_t)bt * 16 * (LDA * 2) + (uint32_t)kc * 32;
                LDSM4(bh[bt], bd + BH_OFF);
                LDSM4(bl[bt], bd + BL_OFF);
            }
#pragma unroll
            for (int mt = 0; mt < 4; ++mt)
#pragma unroll
                for (int nt = 0; nt < 4; ++nt) {
                    uint32_t b0h = bh[nt >> 1][(nt & 1) * 2], b1h = bh[nt >> 1][(nt & 1) * 2 + 1];
                    uint32_t b0l = bl[nt >> 1][(nt & 1) * 2], b1l = bl[nt >> 1][(nt & 1) * 2 + 1];
                    MMA(acc[mt][nt], ah[mt], b0h, b1h);
                    MMA(acc[mt][nt], ah[mt], b0l, b1l);
                    MMA(acc[mt][nt], al[mt], b0h, b1h);
                }
        }
        __syncthreads();  // all reads done before next u overwrites A/B
    }

    // epilogue: mask + scatter-add
#pragma unroll
    for (int mt = 0; mt < 4; ++mt) {
        int e1 = e0 + m0w + mt * 16 + (l >> 2);
        int e2 = e1 + 8;
        float d1 = dist[e1], d2 = dist[e2];
        bool ok1 = (d1 <= 8.0f), ok2 = (d2 <= 8.0f);
        float* r1 = g_msg + (long long)eidx[N_EDGES + e1] * UNITS;
        float* r2 = g_msg + (long long)eidx[N_EDGES + e2] * UNITS;
#pragma unroll
        for (int nt = 0; nt < 4; ++nt) {
            int n = n0w + nt * 8 + (l & 3) * 2;
            if (ok1) {
                atomicAdd(r1 + n,     acc[mt][nt][0]);
                atomicAdd(r1 + n + 1, acc[mt][nt][1]);
            }
            if (ok2) {
                atomicAdd(r2 + n,     acc[mt][nt][2]);
                atomicAdd(r2 + n + 1, acc[mt][nt][3]);
            }
        }
    }
}

// ---------------------------------------------------------------------------
// kernel 4: out = silu(messages)
// ---------------------------------------------------------------------------
__global__ void out_kernel(float* __restrict__ out) {
    int i = blockIdx.x * blockDim.x + threadIdx.x;
    if (i < N_NODES * UNITS) {
        float x = g_msg[i];
        out[i] = x / (1.0f + expf(-x));
    }
}

// ---------------------------------------------------------------------------
extern "C" void kernel_launch(void* const* d_in, const int* in_sizes, int n_in,
                              void* d_out, int out_size) {
    const float* nf   = (const float*)d_in[0];
    const int*   eidx = (const int*)  d_in[1];
    const float* dist = (const float*)d_in[2];
    const float* W1   = (const float*)d_in[3];
    const float* b1   = (const float*)d_in[4];
    const float* W2   = (const float*)d_in[5];
    const float* b2   = (const float*)d_in[6];
    const float* Wt   = (const float*)d_in[7];
    float* out = (float*)d_out;

    const int PREP_SMEM = (16384 + 6400 + 128 + 64 * 129 + 64 * 51) * 4;
    cudaFuncSetAttribute(prep_kernel, cudaFuncAttributeMaxDynamicSharedMemorySize, PREP_SMEM);
    cudaFuncSetAttribute(conv_kernel, cudaFuncAttributeMaxDynamicSharedMemorySize, CONV_SMEM);

    zero_msg_kernel<<<(N_NODES * UNITS) / 1024, 1024>>>();
    w2_convert_kernel<<<129 * 2048 / 256, 256>>>(W2, b2);
    prep_kernel<<<N_EDGES / 64, 256, PREP_SMEM>>>(nf, eidx, dist, W1, b1, Wt);
    conv_kernel<<<dim3(N_EDGES / 128, 2), 256, CONV_SMEM>>>(eidx, dist);
    out_kernel<<<(N_NODES * UNITS + 255) / 256, 256>>>(out);
}

// round 9
// speedup vs baseline: 6.3922x; 1.7906x over previous
#include <cuda_runtime.h>
#include <cuda_fp16.h>
#include <math.h>
#include <stdint.h>

// ---------------------------------------------------------------------------
// ContinuousFilterConv, mma.sync fp16 (legacy tensor path; harness = sm_100 base).
//   C[e,i] = sum_u h[e,u] * P_u[e,i],  P_u = t @ W2'_u   (u=128 row: W2'=b2, h=1)
//   t split th+tl (fp16 pair, exact to 2^-22); W2 single fp16 (err ~2.8e-4).
//   Per u: 2 MMA passes (th*B + tl*B) into reg accum P, then fp32 C += h*P.
//   A-side fragments fixed across u; B double-buffered via cp.async.
// ---------------------------------------------------------------------------

#define N_NODES 20000
#define N_EDGES 8192
#define UNITS   128
#define NGAUSS  50
#define LDA     136            // padded row (fp16 elems) = 272 B

// ---- gmem scratch (static only) ----
__device__ __align__(16) float g_hT[129 * N_EDGES];   // hT[u][e], row 128 == 1
__device__ __align__(16) float g_t [N_EDGES * UNITS]; // t[e][j]
__device__ uint4 g_B4[129 * 2176];                    // W2'_u fp16, padded rows
__device__ __align__(16) float g_msg[N_NODES * UNITS];

// ---- helpers ----
__device__ __forceinline__ uint32_t smem_u32(const void* p) {
    uint32_t a;
    asm("{ .reg .u64 t; cvta.to.shared.u64 t, %1; cvt.u32.u64 %0, t; }" : "=r"(a) : "l"(p));
    return a;
}
__device__ __forceinline__ void cp16(uint32_t saddr, const void* g) {
    asm volatile("cp.async.cg.shared.global [%0], [%1], 16;" :: "r"(saddr), "l"(g) : "memory");
}
#define CP_COMMIT() asm volatile("cp.async.commit_group;" ::: "memory")
#define CP_WAIT0()  asm volatile("cp.async.wait_group 0;" ::: "memory")

#define LDSM4(R, A) \
    asm volatile("ldmatrix.sync.aligned.m8n8.x4.shared.b16 {%0,%1,%2,%3}, [%4];" \
        : "=r"((R)[0]), "=r"((R)[1]), "=r"((R)[2]), "=r"((R)[3]) : "r"(A))

#define MMA(C, A, B0, B1) \
    asm volatile("mma.sync.aligned.m16n8k16.row.col.f32.f16.f16.f32 " \
        "{%0,%1,%2,%3},{%4,%5,%6,%7},{%8,%9},{%0,%1,%2,%3};" \
        : "+f"((C)[0]), "+f"((C)[1]), "+f"((C)[2]), "+f"((C)[3]) \
        : "r"((A)[0]), "r"((A)[1]), "r"((A)[2]), "r"((A)[3]), "r"(B0), "r"(B1))

__device__ __forceinline__ uint32_t pack_h2(float x0, float x1) {
    return (uint32_t)__half_as_ushort(__float2half(x0))
         | ((uint32_t)__half_as_ushort(__float2half(x1)) << 16);
}
__device__ __forceinline__ float silu_f(float x) { return x / (1.0f + expf(-x)); }

// ---------------------------------------------------------------------------
// kernel 0: zero message accumulator (float4)
// ---------------------------------------------------------------------------
__global__ void zero_msg_kernel() {
    int i = blockIdx.x * blockDim.x + threadIdx.x;  // grid sized exactly (640000)
    ((float4*)g_msg)[i] = make_float4(0.f, 0.f, 0.f, 0.f);
}

// ---------------------------------------------------------------------------
// kernel 1: W2/b2 -> fp16, padded rows (17 uint4 per 128-elem row)
// ---------------------------------------------------------------------------
__global__ __launch_bounds__(256) void w2_convert_kernel(
    const float* __restrict__ W2, const float* __restrict__ b2)
{
    int g  = blockIdx.x * 256 + threadIdx.x;       // < 129*2048
    int u  = g >> 11, rem = g & 2047;
    int i  = rem >> 4, jq = rem & 15;
    const float* row = (u < 128) ? (W2 + (long long)u * 16384) : b2;
    float4 a = *(const float4*)(row + i * 128 + jq * 8);
    float4 b = *(const float4*)(row + i * 128 + jq * 8 + 4);
    uint4 o;
    o.x = pack_h2(a.x, a.y);
    o.y = pack_h2(a.z, a.w);
    o.z = pack_h2(b.x, b.y);
    o.w = pack_h2(b.z, b.w);
    g_B4[u * 2176 + i * 17 + jq] = o;
}

// ---------------------------------------------------------------------------
// kernel 2: per-edge h (gaussian -> dense -> silu, transposed) + t (gather @ Wt)
// ---------------------------------------------------------------------------
__global__ __launch_bounds__(256) void prep_kernel(
    const float* __restrict__ nf, const int* __restrict__ eidx,
    const float* __restrict__ dist, const float* __restrict__ W1,
    const float* __restrict__ b1, const float* __restrict__ Wt)
{
    extern __shared__ float sm[];
    float* Wt_s = sm;                       // 16384
    float* W1_s = Wt_s + 16384;             // 6400
    float* b1_s = W1_s + 6400;              // 128
    float* X_s  = b1_s + 128;               // 64*129
    float* df_s = X_s + 64 * 129;           // 64*51
    const int tid = threadIdx.x;
    const int e0  = blockIdx.x * 64;

    for (int idx = tid; idx < 16384; idx += 256) Wt_s[idx] = Wt[idx];
    for (int idx = tid; idx < NGAUSS * UNITS; idx += 256) W1_s[idx] = W1[idx];
    if (tid < 128) b1_s[tid] = b1[tid];
    for (int idx = tid; idx < 64 * NGAUSS; idx += 256) {
        int e = idx & 63, g = idx >> 6;
        float d = dist[e0 + e];
        float c = (30.0f / 49.0f) * (float)g;
        float x = d - c;
        df_s[e * 51 + g] = expf(-10.0f * x * x);
    }
    for (int idx = tid; idx < 64 * UNITS; idx += 256) {
        int e = idx >> 7, j = idx & 127;
        int s = eidx[e0 + e];
        X_s[e * 129 + j] = nf[(long long)s * UNITS + j];
    }
    __syncthreads();

    for (int o = tid; o < 64 * UNITS; o += 256) {
        int u = o >> 6, e = o & 63;
        float acc = b1_s[u];
        const float* dfr = df_s + e * 51;
#pragma unroll
        for (int g = 0; g < NGAUSS; ++g) acc += dfr[g] * W1_s[g * UNITS + u];
        g_hT[u * N_EDGES + e0 + e] = silu_f(acc);
    }
    for (int idx = tid; idx < 64; idx += 256)
        g_hT[128 * N_EDGES + e0 + idx] = 1.0f;

    for (int o = tid; o < 64 * UNITS; o += 256) {
        int e = o >> 7, u = o & 127;
        float acc = 0.0f;
        const float* xr = X_s + e * 129;
#pragma unroll
        for (int j = 0; j < UNITS; ++j) acc += xr[j] * Wt_s[j * UNITS + u];
        g_t[(e0 + e) * UNITS + u] = acc;
    }
}

// ---------------------------------------------------------------------------
// kernel 3: main GEMM. CTA = 128 edges x 128 i; grid.y splits u (0..64 / 65..128).
// 8 warps 2(M)x4(N), each 64M x 32N. A (t hi/lo) fixed; B double-buffered.
// ---------------------------------------------------------------------------
#define TH_OFF 0
#define TL_OFF 34816
#define HS_OFF 69632
#define B0_OFF 102912
#define B1_OFF 137728
#define CONV_SMEM 172544

__global__ __launch_bounds__(256, 1) void conv_kernel(
    const int* __restrict__ eidx, const float* __restrict__ dist)
{
    extern __shared__ char smem[];
    const uint32_t sb = smem_u32(smem);
    const int tid = threadIdx.x, l = tid & 31, wid = tid >> 5;
    const int e0 = blockIdx.x * 128;
    const int ub = blockIdx.y ? 65 : 0;
    const int ue = blockIdx.y ? 129 : 65;
    const int nu = ue - ub;

    // async prefetch: B[ub] -> buf0, and the whole h slice -> Hs
    {
        const uint4* gb = g_B4 + ub * 2176;
        for (int k = tid; k < 2176; k += 256) cp16(sb + B0_OFF + k * 16, gb + k);
        for (int k = tid; k < nu * 32; k += 256) {
            int u_l = k >> 5, off = k & 31;
            const uint4* src = (const uint4*)(g_hT + (ub + u_l) * N_EDGES + e0) + off;
            cp16(sb + HS_OFF + k * 16, src);
        }
        CP_COMMIT();
    }

    // convert t tile -> fp16 hi/lo (padded rows), overlaps with cp.async
    for (int idx = tid; idx < 128 * 128; idx += 256) {
        int e = idx >> 7, j = idx & 127;
        float x = g_t[(e0 + e) * UNITS + j];
        __half th = __float2half(x);
        __half tl = __float2half(x - __half2float(th));
        *(__half*)(smem + TH_OFF + e * (LDA * 2) + j * 2) = th;
        *(__half*)(smem + TL_OFF + e * (LDA * 2) + j * 2) = tl;
    }

    const int m0w = (wid & 1) * 64;
    const int n0w = (wid >> 1) * 32;
    const uint32_t aOff = (uint32_t)(m0w + (l & 7) + ((l >> 3) & 1) * 8) * (LDA * 2)
                        + (uint32_t)(l >> 4) * 16;
    const uint32_t bOff = (uint32_t)(n0w + (l & 7) + ((l >> 4) & 1) * 8) * (LDA * 2)
                        + (uint32_t)((l >> 3) & 1) * 16;
    const float* hbase = (const float*)(smem + HS_OFF);

    float accC[4][4][4];
#pragma unroll
    for (int mt = 0; mt < 4; ++mt)
#pragma unroll
        for (int nt = 0; nt < 4; ++nt)
#pragma unroll
            for (int q = 0; q < 4; ++q) accC[mt][nt][q] = 0.0f;

    for (int u = ub; u < ue; ++u) {
        const int cur = (u - ub) & 1;
        CP_WAIT0();
        __syncthreads();   // buf[cur]+Hs ready; all reads of buf[1-cur] done

        if (u + 1 < ue) {  // prefetch next B into the other buffer
            const uint4* gb = g_B4 + (u + 1) * 2176;
            uint32_t dst = sb + (cur ? B0_OFF : B1_OFF);
            for (int k = tid; k < 2176; k += 256) cp16(dst + k * 16, gb + k);
            CP_COMMIT();
        }

        const uint32_t bBase = sb + (cur ? B1_OFF : B0_OFF) + bOff;

        float accP[4][4][4];
#pragma unroll
        for (int mt = 0; mt < 4; ++mt)
#pragma unroll
            for (int nt = 0; nt < 4; ++nt)
#pragma unroll
                for (int q = 0; q < 4; ++q) accP[mt][nt][q] = 0.0f;

#pragma unroll
        for (int kc = 0; kc < 8; ++kc) {
            uint32_t ah[4][4], al[4][4], bf[2][4];
#pragma unroll
            for (int mt = 0; mt < 4; ++mt) {
                uint32_t ad = sb + aOff + (uint32_t)mt * 16 * (LDA * 2) + (uint32_t)kc * 32;
                LDSM4(ah[mt], ad + TH_OFF);
                LDSM4(al[mt], ad + TL_OFF);
            }
#pragma unroll
            for (int bt = 0; bt < 2; ++bt) {
                uint32_t bd = bBase + (uint32_t)bt * 16 * (LDA * 2) + (uint32_t)kc * 32;
                LDSM4(bf[bt], bd);
            }
#pragma unroll
            for (int mt = 0; mt < 4; ++mt)
#pragma unroll
                for (int nt = 0; nt < 4; ++nt) {
                    uint32_t b0 = bf[nt >> 1][(nt & 1) * 2];
                    uint32_t b1 = bf[nt >> 1][(nt & 1) * 2 + 1];
                    MMA(accP[mt][nt], ah[mt], b0, b1);
                    MMA(accP[mt][nt], al[mt], b0, b1);
                }
        }

        // C += h[e,u] * P   (fp32, exact h application)
        const float* hrow = hbase + (u - ub) * 128;
#pragma unroll
        for (int mt = 0; mt < 4; ++mt) {
            int r = m0w + mt * 16 + (l >> 2);
            float h1 = hrow[r];
            float h2 = hrow[r + 8];
#pragma unroll
            for (int nt = 0; nt < 4; ++nt) {
                accC[mt][nt][0] += h1 * accP[mt][nt][0];
                accC[mt][nt][1] += h1 * accP[mt][nt][1];
                accC[mt][nt][2] += h2 * accP[mt][nt][2];
                accC[mt][nt][3] += h2 * accP[mt][nt][3];
            }
        }
    }

    // epilogue: cutoff mask + scatter-add
#pragma unroll
    for (int mt = 0; mt < 4; ++mt) {
        int e1 = e0 + m0w + mt * 16 + (l >> 2);
        int e2 = e1 + 8;
        float d1 = dist[e1], d2 = dist[e2];
        bool ok1 = (d1 <= 8.0f), ok2 = (d2 <= 8.0f);
        float* r1 = g_msg + (long long)eidx[N_EDGES + e1] * UNITS;
        float* r2 = g_msg + (long long)eidx[N_EDGES + e2] * UNITS;
#pragma unroll
        for (int nt = 0; nt < 4; ++nt) {
            int n = n0w + nt * 8 + (l & 3) * 2;
            if (ok1) {
                atomicAdd(r1 + n,     accC[mt][nt][0]);
                atomicAdd(r1 + n + 1, accC[mt][nt][1]);
            }
            if (ok2) {
                atomicAdd(r2 + n,     accC[mt][nt][2]);
                atomicAdd(r2 + n + 1, accC[mt][nt][3]);
            }
        }
    }
}

// ---------------------------------------------------------------------------
// kernel 4: out = silu(messages), float4
// ---------------------------------------------------------------------------
__global__ void out_kernel(float* __restrict__ out) {
    int i = blockIdx.x * blockDim.x + threadIdx.x;  // grid sized exactly (640000)
    float4 x = ((const float4*)g_msg)[i];
    float4 y;
    y.x = silu_f(x.x); y.y = silu_f(x.y); y.z = silu_f(x.z); y.w = silu_f(x.w);
    ((float4*)out)[i] = y;
}

// ---------------------------------------------------------------------------
extern "C" void kernel_launch(void* const* d_in, const int* in_sizes, int n_in,
                              void* d_out, int out_size) {
    const float* nf   = (const float*)d_in[0];
    const int*   eidx = (const int*)  d_in[1];
    const float* dist = (const float*)d_in[2];
    const float* W1   = (const float*)d_in[3];
    const float* b1   = (const float*)d_in[4];
    const float* W2   = (const float*)d_in[5];
    const float* b2   = (const float*)d_in[6];
    const float* Wt   = (const float*)d_in[7];
    float* out = (float*)d_out;

    const int PREP_SMEM = (16384 + 6400 + 128 + 64 * 129 + 64 * 51) * 4;
    cudaFuncSetAttribute(prep_kernel, cudaFuncAttributeMaxDynamicSharedMemorySize, PREP_SMEM);
    cudaFuncSetAttribute(conv_kernel, cudaFuncAttributeMaxDynamicSharedMemorySize, CONV_SMEM);

    zero_msg_kernel<<<(N_NODES * UNITS / 4) / 256, 256>>>();
    w2_convert_kernel<<<129 * 2048 / 256, 256>>>(W2, b2);
    prep_kernel<<<N_EDGES / 64, 256, PREP_SMEM>>>(nf, eidx, dist, W1, b1, Wt);
    conv_kernel<<<dim3(N_EDGES / 128, 2), 256, CONV_SMEM>>>(eidx, dist);
    out_kernel<<<(N_NODES * UNITS / 4) / 256, 256>>>(out);
}

// round 10
// speedup vs baseline: 9.6516x; 1.5099x over previous
#include <cuda_runtime.h>
#include <cuda_fp16.h>
#include <math.h>
#include <stdint.h>

// ---------------------------------------------------------------------------
// ContinuousFilterConv, mma.sync fp16 single-pass (legacy tensor path).
//   C[e,i] = sum_u h[e,u] * P_u[e,i],  P_u = t @ W2'_u  (u=128 row: W2'=b2, h=1)
//   t and W2 in fp16 (combined rel err ~3e-4 < 1e-3); h applied in fp32.
//   A (t) fragments fixed across u; B triple-buffered via cp.async (wait_group 1).
// ---------------------------------------------------------------------------

#define N_NODES 20000
#define N_EDGES 8192
#define UNITS   128
#define NGAUSS  50
#define LDA     136            // padded row (fp16 elems) = 272 B

// ---- gmem scratch (static only) ----
__device__ __align__(16) float  g_hT[129 * N_EDGES];     // hT[u][e], row 128 == 1
__device__ __align__(16) __half g_th[N_EDGES * LDA];     // t fp16, padded rows
__device__ uint4 g_B4[129 * 2176];                       // W2'_u fp16, padded rows
__device__ __align__(16) float g_msg[N_NODES * UNITS];

// ---- helpers ----
__device__ __forceinline__ uint32_t smem_u32(const void* p) {
    uint32_t a;
    asm("{ .reg .u64 t; cvta.to.shared.u64 t, %1; cvt.u32.u64 %0, t; }" : "=r"(a) : "l"(p));
    return a;
}
__device__ __forceinline__ void cp16(uint32_t saddr, const void* g) {
    asm volatile("cp.async.cg.shared.global [%0], [%1], 16;" :: "r"(saddr), "l"(g) : "memory");
}
#define CP_COMMIT() asm volatile("cp.async.commit_group;" ::: "memory")
#define CP_WAIT1()  asm volatile("cp.async.wait_group 1;" ::: "memory")

#define LDSM4(R, A) \
    asm volatile("ldmatrix.sync.aligned.m8n8.x4.shared.b16 {%0,%1,%2,%3}, [%4];" \
        : "=r"((R)[0]), "=r"((R)[1]), "=r"((R)[2]), "=r"((R)[3]) : "r"(A))

#define MMA(C, A, B0, B1) \
    asm volatile("mma.sync.aligned.m16n8k16.row.col.f32.f16.f16.f32 " \
        "{%0,%1,%2,%3},{%4,%5,%6,%7},{%8,%9},{%0,%1,%2,%3};" \
        : "+f"((C)[0]), "+f"((C)[1]), "+f"((C)[2]), "+f"((C)[3]) \
        : "r"((A)[0]), "r"((A)[1]), "r"((A)[2]), "r"((A)[3]), "r"(B0), "r"(B1))

__device__ __forceinline__ uint32_t pack_h2(float x0, float x1) {
    return (uint32_t)__half_as_ushort(__float2half(x0))
         | ((uint32_t)__half_as_ushort(__float2half(x1)) << 16);
}
__device__ __forceinline__ float silu_f(float x) { return x / (1.0f + expf(-x)); }

// ---------------------------------------------------------------------------
// kernel 0: zero message accumulator (float4)
// ---------------------------------------------------------------------------
__global__ void zero_msg_kernel() {
    int i = blockIdx.x * blockDim.x + threadIdx.x;  // grid sized exactly (160000)
    ((float4*)g_msg)[i] = make_float4(0.f, 0.f, 0.f, 0.f);
}

// ---------------------------------------------------------------------------
// kernel 1: W2/b2 -> fp16, padded rows (17 uint4 per 128-elem row)
// ---------------------------------------------------------------------------
__global__ __launch_bounds__(256) void w2_convert_kernel(
    const float* __restrict__ W2, const float* __restrict__ b2)
{
    int g  = blockIdx.x * 256 + threadIdx.x;       // < 129*2048
    int u  = g >> 11, rem = g & 2047;
    int i  = rem >> 4, jq = rem & 15;
    const float* row = (u < 128) ? (W2 + (long long)u * 16384) : b2;
    float4 a = *(const float4*)(row + i * 128 + jq * 8);
    float4 b = *(const float4*)(row + i * 128 + jq * 8 + 4);
    uint4 o;
    o.x = pack_h2(a.x, a.y);
    o.y = pack_h2(a.z, a.w);
    o.z = pack_h2(b.x, b.y);
    o.w = pack_h2(b.z, b.w);
    g_B4[u * 2176 + i * 17 + jq] = o;
}

// ---------------------------------------------------------------------------
// kernel 2: per-edge h (gaussian -> dense -> silu, transposed) + t (gather @ Wt)
// t written directly as fp16 in padded LDSM layout.
// ---------------------------------------------------------------------------
__global__ __launch_bounds__(256) void prep_kernel(
    const float* __restrict__ nf, const int* __restrict__ eidx,
    const float* __restrict__ dist, const float* __restrict__ W1,
    const float* __restrict__ b1, const float* __restrict__ Wt)
{
    extern __shared__ float sm[];
    float* Wt_s = sm;                       // 16384
    float* W1_s = Wt_s + 16384;             // 6400
    float* b1_s = W1_s + 6400;              // 128
    float* X_s  = b1_s + 128;               // 64*129
    float* df_s = X_s + 64 * 129;           // 64*51
    const int tid = threadIdx.x;
    const int e0  = blockIdx.x * 64;

    for (int idx = tid; idx < 16384; idx += 256) Wt_s[idx] = Wt[idx];
    for (int idx = tid; idx < NGAUSS * UNITS; idx += 256) W1_s[idx] = W1[idx];
    if (tid < 128) b1_s[tid] = b1[tid];
    for (int idx = tid; idx < 64 * NGAUSS; idx += 256) {
        int e = idx & 63, g = idx >> 6;
        float d = dist[e0 + e];
        float c = (30.0f / 49.0f) * (float)g;
        float x = d - c;
        df_s[e * 51 + g] = expf(-10.0f * x * x);
    }
    for (int idx = tid; idx < 64 * UNITS; idx += 256) {
        int e = idx >> 7, j = idx & 127;
        int s = eidx[e0 + e];
        X_s[e * 129 + j] = nf[(long long)s * UNITS + j];
    }
    __syncthreads();

    for (int o = tid; o < 64 * UNITS; o += 256) {
        int u = o >> 6, e = o & 63;
        float acc = b1_s[u];
        const float* dfr = df_s + e * 51;
#pragma unroll
        for (int g = 0; g < NGAUSS; ++g) acc += dfr[g] * W1_s[g * UNITS + u];
        g_hT[u * N_EDGES + e0 + e] = silu_f(acc);
    }
    for (int idx = tid; idx < 64; idx += 256)
        g_hT[128 * N_EDGES + e0 + idx] = 1.0f;

    for (int o = tid; o < 64 * UNITS; o += 256) {
        int e = o >> 7, u = o & 127;
        float acc = 0.0f;
        const float* xr = X_s + e * 129;
#pragma unroll
        for (int j = 0; j < UNITS; ++j) acc += xr[j] * Wt_s[j * UNITS + u];
        g_th[(e0 + e) * LDA + u] = __float2half(acc);
    }
}

// ---------------------------------------------------------------------------
// kernel 3: main GEMM. CTA = 128 edges x 128 i; grid.y splits u (0..64 / 65..128).
// 8 warps 2(M)x4(N), each 64M x 32N. A (t fp16) fixed; B triple-buffered.
// ---------------------------------------------------------------------------
#define TH_OFF 0
#define HS_OFF 34816
#define B_OFF  68096
#define BBUF   34816
#define CONV_SMEM 172544   // 68096 + 3*34816

__global__ __launch_bounds__(256, 1) void conv_kernel(
    const int* __restrict__ eidx, const float* __restrict__ dist)
{
    extern __shared__ char smem[];
    const uint32_t sb = smem_u32(smem);
    const int tid = threadIdx.x, l = tid & 31, wid = tid >> 5;
    const int e0 = blockIdx.x * 128;
    const int ub = blockIdx.y ? 65 : 0;
    const int ue = blockIdx.y ? 129 : 65;
    const int nu = ue - ub;

    // G0: B[ub] -> buf0, th tile, h slice
    {
        const uint4* gb = g_B4 + ub * 2176;
        for (int k = tid; k < 2176; k += 256) cp16(sb + B_OFF + k * 16, gb + k);
        const uint4* gt = (const uint4*)(g_th + (long long)e0 * LDA);
        for (int k = tid; k < 2176; k += 256) cp16(sb + TH_OFF + k * 16, gt + k);
        for (int k = tid; k < nu * 32; k += 256) {
            int u_l = k >> 5, off = k & 31;
            cp16(sb + HS_OFF + k * 16,
                 (const uint4*)(g_hT + (ub + u_l) * N_EDGES + e0) + off);
        }
        CP_COMMIT();
    }
    // G1: B[ub+1] -> buf1
    {
        const uint4* gb = g_B4 + (ub + 1) * 2176;
        for (int k = tid; k < 2176; k += 256) cp16(sb + B_OFF + BBUF + k * 16, gb + k);
        CP_COMMIT();
    }

    const int m0w = (wid & 1) * 64;
    const int n0w = (wid >> 1) * 32;
    const uint32_t aOff = (uint32_t)(m0w + (l & 7) + ((l >> 3) & 1) * 8) * (LDA * 2)
                        + (uint32_t)(l >> 4) * 16;
    const uint32_t bOff = (uint32_t)(n0w + (l & 7) + ((l >> 4) & 1) * 8) * (LDA * 2)
                        + (uint32_t)((l >> 3) & 1) * 16;
    const float* hbase = (const float*)(smem + HS_OFF);

    float accC[4][4][4];
#pragma unroll
    for (int mt = 0; mt < 4; ++mt)
#pragma unroll
        for (int nt = 0; nt < 4; ++nt)
#pragma unroll
            for (int q = 0; q < 4; ++q) accC[mt][nt][q] = 0.0f;

    for (int u = ub; u < ue; ++u) {
        const int k = u - ub;
        CP_WAIT1();        // all groups but the newest complete -> buf[k%3] ready
        __syncthreads();

        // prefetch B[u+2] into buf[(k+2)%3]; commit exactly one group per iter
        if (u + 2 < ue) {
            const uint4* gb = g_B4 + (u + 2) * 2176;
            uint32_t dst = sb + B_OFF + (uint32_t)((k + 2) % 3) * BBUF;
            for (int kk = tid; kk < 2176; kk += 256) cp16(dst + kk * 16, gb + kk);
        }
        CP_COMMIT();

        const uint32_t bBase = sb + B_OFF + (uint32_t)(k % 3) * BBUF + bOff;

        float accP[4][4][4];
#pragma unroll
        for (int mt = 0; mt < 4; ++mt)
#pragma unroll
            for (int nt = 0; nt < 4; ++nt)
#pragma unroll
                for (int q = 0; q < 4; ++q) accP[mt][nt][q] = 0.0f;

#pragma unroll
        for (int kc = 0; kc < 8; ++kc) {
            uint32_t af[4][4], bf[2][4];
#pragma unroll
            for (int mt = 0; mt < 4; ++mt)
                LDSM4(af[mt], sb + TH_OFF + aOff
                              + (uint32_t)mt * 16 * (LDA * 2) + (uint32_t)kc * 32);
#pragma unroll
            for (int bt = 0; bt < 2; ++bt)
                LDSM4(bf[bt], bBase + (uint32_t)bt * 16 * (LDA * 2) + (uint32_t)kc * 32);
#pragma unroll
            for (int mt = 0; mt < 4; ++mt)
#pragma unroll
                for (int nt = 0; nt < 4; ++nt)
                    MMA(accP[mt][nt],
                        af[mt],
                        bf[nt >> 1][(nt & 1) * 2],
                        bf[nt >> 1][(nt & 1) * 2 + 1]);
        }

        // C += h[e,u] * P   (fp32, exact h application)
        const float* hrow = hbase + k * 128;
#pragma unroll
        for (int mt = 0; mt < 4; ++mt) {
            int r = m0w + mt * 16 + (l >> 2);
            float h1 = hrow[r];
            float h2 = hrow[r + 8];
#pragma unroll
            for (int nt = 0; nt < 4; ++nt) {
                accC[mt][nt][0] += h1 * accP[mt][nt][0];
                accC[mt][nt][1] += h1 * accP[mt][nt][1];
                accC[mt][nt][2] += h2 * accP[mt][nt][2];
                accC[mt][nt][3] += h2 * accP[mt][nt][3];
            }
        }
    }

    // epilogue: cutoff mask + scatter-add
#pragma unroll
    for (int mt = 0; mt < 4; ++mt) {
        int e1 = e0 + m0w + mt * 16 + (l >> 2);
        int e2 = e1 + 8;
        float d1 = dist[e1], d2 = dist[e2];
        bool ok1 = (d1 <= 8.0f), ok2 = (d2 <= 8.0f);
        float* r1 = g_msg + (long long)eidx[N_EDGES + e1] * UNITS;
        float* r2 = g_msg + (long long)eidx[N_EDGES + e2] * UNITS;
#pragma unroll
        for (int nt = 0; nt < 4; ++nt) {
            int n = n0w + nt * 8 + (l & 3) * 2;
            if (ok1) {
                atomicAdd(r1 + n,     accC[mt][nt][0]);
                atomicAdd(r1 + n + 1, accC[mt][nt][1]);
            }
            if (ok2) {
                atomicAdd(r2 + n,     accC[mt][nt][2]);
                atomicAdd(r2 + n + 1, accC[mt][nt][3]);
            }
        }
    }
}

// ---------------------------------------------------------------------------
// kernel 4: out = silu(messages), float4
// ---------------------------------------------------------------------------
__global__ void out_kernel(float* __restrict__ out) {
    int i = blockIdx.x * blockDim.x + threadIdx.x;  // grid sized exactly (160000)
    float4 x = ((const float4*)g_msg)[i];
    float4 y;
    y.x = silu_f(x.x); y.y = silu_f(x.y); y.z = silu_f(x.z); y.w = silu_f(x.w);
    ((float4*)out)[i] = y;
}

// ---------------------------------------------------------------------------
extern "C" void kernel_launch(void* const* d_in, const int* in_sizes, int n_in,
                              void* d_out, int out_size) {
    const float* nf   = (const float*)d_in[0];
    const int*   eidx = (const int*)  d_in[1];
    const float* dist = (const float*)d_in[2];
    const float* W1   = (const float*)d_in[3];
    const float* b1   = (const float*)d_in[4];
    const float* W2   = (const float*)d_in[5];
    const float* b2   = (const float*)d_in[6];
    const float* Wt   = (const float*)d_in[7];
    float* out = (float*)d_out;

    const int PREP_SMEM = (16384 + 6400 + 128 + 64 * 129 + 64 * 51) * 4;
    cudaFuncSetAttribute(prep_kernel, cudaFuncAttributeMaxDynamicSharedMemorySize, PREP_SMEM);
    cudaFuncSetAttribute(conv_kernel, cudaFuncAttributeMaxDynamicSharedMemorySize, CONV_SMEM);

    zero_msg_kernel<<<(N_NODES * UNITS / 4) / 256, 256>>>();
    w2_convert_kernel<<<129 * 2048 / 256, 256>>>(W2, b2);
    prep_kernel<<<N_EDGES / 64, 256, PREP_SMEM>>>(nf, eidx, dist, W1, b1, Wt);
    conv_kernel<<<dim3(N_EDGES / 128, 2), 256, CONV_SMEM>>>(eidx, dist);
    out_kernel<<<(N_NODES * UNITS / 4) / 256, 256>>>(out);
}

// round 11
// speedup vs baseline: 9.9276x; 1.0286x over previous
#include <cuda_runtime.h>
#include <cuda_fp16.h>
#include <math.h>
#include <stdint.h>

// ---------------------------------------------------------------------------
// ContinuousFilterConv, mma.sync fp16 single-pass, pair-pipelined.
//   C[e,i] = sum_u h[e,u] * P_u[e,i],  P_u = t @ W2'_u  (u=128 row: W2'=b2, h=1)
//   t, W2 fp16 (rel err ~3e-4); h applied in fp32 per u.
//   Two u processed per pipeline stage sharing A (t) fragments; B 4-slab ring.
// ---------------------------------------------------------------------------

#define N_NODES 20000
#define N_EDGES 8192
#define UNITS   128
#define NGAUSS  50
#define LDA     136            // padded row (fp16 elems) = 272 B

// ---- gmem scratch (static only) ----
__device__ __align__(16) float  g_hT[129 * N_EDGES];     // hT[u][e], row 128 == 1
__device__ __align__(16) __half g_th[N_EDGES * LDA];     // t fp16, padded rows
__device__ uint4 g_B4[129 * 2176];                       // W2'_u fp16, padded rows
__device__ __align__(16) float g_msg[N_NODES * UNITS];

// ---- helpers ----
__device__ __forceinline__ uint32_t smem_u32(const void* p) {
    uint32_t a;
    asm("{ .reg .u64 t; cvta.to.shared.u64 t, %1; cvt.u32.u64 %0, t; }" : "=r"(a) : "l"(p));
    return a;
}
__device__ __forceinline__ void cp16(uint32_t saddr, const void* g) {
    asm volatile("cp.async.cg.shared.global [%0], [%1], 16;" :: "r"(saddr), "l"(g) : "memory");
}
#define CP_COMMIT() asm volatile("cp.async.commit_group;" ::: "memory")
#define CP_WAIT0()  asm volatile("cp.async.wait_group 0;" ::: "memory")

#define LDSM4(R, A) \
    asm volatile("ldmatrix.sync.aligned.m8n8.x4.shared.b16 {%0,%1,%2,%3}, [%4];" \
        : "=r"((R)[0]), "=r"((R)[1]), "=r"((R)[2]), "=r"((R)[3]) : "r"(A))

#define MMA(C, A, B0, B1) \
    asm volatile("mma.sync.aligned.m16n8k16.row.col.f32.f16.f16.f32 " \
        "{%0,%1,%2,%3},{%4,%5,%6,%7},{%8,%9},{%0,%1,%2,%3};" \
        : "+f"((C)[0]), "+f"((C)[1]), "+f"((C)[2]), "+f"((C)[3]) \
        : "r"((A)[0]), "r"((A)[1]), "r"((A)[2]), "r"((A)[3]), "r"(B0), "r"(B1))

__device__ __forceinline__ uint32_t pack_h2(float x0, float x1) {
    return (uint32_t)__half_as_ushort(__float2half(x0))
         | ((uint32_t)__half_as_ushort(__float2half(x1)) << 16);
}
__device__ __forceinline__ float silu_f(float x) { return x / (1.0f + expf(-x)); }

// ---------------------------------------------------------------------------
// kernel 1: W2/b2 -> fp16 padded rows + grid-stride zero of g_msg (fused)
// grid = 1032 blocks x 256
// ---------------------------------------------------------------------------
__global__ __launch_bounds__(256) void w2_zero_kernel(
    const float* __restrict__ W2, const float* __restrict__ b2)
{
    int g  = blockIdx.x * 256 + threadIdx.x;       // < 129*2048
    int u  = g >> 11, rem = g & 2047;
    int i  = rem >> 4, jq = rem & 15;
    const float* row = (u < 128) ? (W2 + (long long)u * 16384) : b2;
    float4 a = *(const float4*)(row + i * 128 + jq * 8);
    float4 b = *(const float4*)(row + i * 128 + jq * 8 + 4);
    uint4 o;
    o.x = pack_h2(a.x, a.y);
    o.y = pack_h2(a.z, a.w);
    o.z = pack_h2(b.x, b.y);
    o.w = pack_h2(b.z, b.w);
    g_B4[u * 2176 + i * 17 + jq] = o;
    // zero g_msg (640000 float4)
    for (int k = g; k < N_NODES * UNITS / 4; k += 1032 * 256)
        ((float4*)g_msg)[k] = make_float4(0.f, 0.f, 0.f, 0.f);
}

// ---------------------------------------------------------------------------
// kernel 2: per-edge h (gaussian -> dense -> silu, transposed) + t (gather @ Wt)
// ---------------------------------------------------------------------------
__global__ __launch_bounds__(256) void prep_kernel(
    const float* __restrict__ nf, const int* __restrict__ eidx,
    const float* __restrict__ dist, const float* __restrict__ W1,
    const float* __restrict__ b1, const float* __restrict__ Wt)
{
    extern __shared__ float sm[];
    float* Wt_s = sm;                       // 16384
    float* W1_s = Wt_s + 16384;             // 6400
    float* b1_s = W1_s + 6400;              // 128
    float* X_s  = b1_s + 128;               // 64*129
    float* df_s = X_s + 64 * 129;           // 64*51
    const int tid = threadIdx.x;
    const int e0  = blockIdx.x * 64;

    for (int idx = tid; idx < 16384; idx += 256) Wt_s[idx] = Wt[idx];
    for (int idx = tid; idx < NGAUSS * UNITS; idx += 256) W1_s[idx] = W1[idx];
    if (tid < 128) b1_s[tid] = b1[tid];
    for (int idx = tid; idx < 64 * NGAUSS; idx += 256) {
        int e = idx & 63, g = idx >> 6;
        float d = dist[e0 + e];
        float c = (30.0f / 49.0f) * (float)g;
        float x = d - c;
        df_s[e * 51 + g] = expf(-10.0f * x * x);
    }
    for (int idx = tid; idx < 64 * UNITS; idx += 256) {
        int e = idx >> 7, j = idx & 127;
        int s = eidx[e0 + e];
        X_s[e * 129 + j] = nf[(long long)s * UNITS + j];
    }
    __syncthreads();

    for (int o = tid; o < 64 * UNITS; o += 256) {
        int u = o >> 6, e = o & 63;
        float acc = b1_s[u];
        const float* dfr = df_s + e * 51;
#pragma unroll
        for (int g = 0; g < NGAUSS; ++g) acc += dfr[g] * W1_s[g * UNITS + u];
        g_hT[u * N_EDGES + e0 + e] = silu_f(acc);
    }
    for (int idx = tid; idx < 64; idx += 256)
        g_hT[128 * N_EDGES + e0 + idx] = 1.0f;

    for (int o = tid; o < 64 * UNITS; o += 256) {
        int e = o >> 7, u = o & 127;
        float acc = 0.0f;
        const float* xr = X_s + e * 129;
#pragma unroll
        for (int j = 0; j < UNITS; ++j) acc += xr[j] * Wt_s[j * UNITS + u];
        g_th[(e0 + e) * LDA + u] = __float2half(acc);
    }
}

// ---------------------------------------------------------------------------
// kernel 3: main GEMM, pair-pipelined. CTA = 128 edges x 128 i; grid.y splits u.
// 8 warps 2(M)x4(N). A fragments shared across the two u of each pair.
// ---------------------------------------------------------------------------
#define TH_OFF 0
#define HS_OFF 34816
#define B_OFF  68096
#define BBUF   34816
#define CONV_SMEM 207360   // 68096 + 4*34816

__global__ __launch_bounds__(256, 1) void conv_kernel(
    const int* __restrict__ eidx, const float* __restrict__ dist)
{
    extern __shared__ char smem[];
    const uint32_t sb = smem_u32(smem);
    const int tid = threadIdx.x, l = tid & 31, wid = tid >> 5;
    const int e0 = blockIdx.x * 128;
    const int ub = blockIdx.y ? 65 : 0;
    const int ue = blockIdx.y ? 129 : 65;
    const int nu = ue - ub;                 // 65 or 64
    const int np = nu >> 1;                 // full pairs
    const int tail = nu & 1;

    // prologue group: B[ub], B[ub+1] -> slabs 0,1; th tile; h slice
    {
        const uint4* gb = g_B4 + ub * 2176;
        for (int k = tid; k < 2 * 2176; k += 256) cp16(sb + B_OFF + k * 16, gb + k);
        const uint4* gt = (const uint4*)(g_th + (long long)e0 * LDA);
        for (int k = tid; k < 2176; k += 256) cp16(sb + TH_OFF + k * 16, gt + k);
        for (int k = tid; k < nu * 32; k += 256) {
            int u_l = k >> 5, off = k & 31;
            cp16(sb + HS_OFF + k * 16,
                 (const uint4*)(g_hT + (ub + u_l) * N_EDGES + e0) + off);
        }
        CP_COMMIT();
    }

    const int m0w = (wid & 1) * 64;
    const int n0w = (wid >> 1) * 32;
    const uint32_t aOff = (uint32_t)(m0w + (l & 7) + ((l >> 3) & 1) * 8) * (LDA * 2)
                        + (uint32_t)(l >> 4) * 16;
    const uint32_t bOff = (uint32_t)(n0w + (l & 7) + ((l >> 4) & 1) * 8) * (LDA * 2)
                        + (uint32_t)((l >> 3) & 1) * 16;
    const float* hbase = (const float*)(smem + HS_OFF);

    float accC[4][4][4];
#pragma unroll
    for (int mt = 0; mt < 4; ++mt)
#pragma unroll
        for (int nt = 0; nt < 4; ++nt)
#pragma unroll
            for (int q = 0; q < 4; ++q) accC[mt][nt][q] = 0.0f;

    for (int p = 0; p < np; ++p) {
        const int k0 = 2 * p;
        CP_WAIT0();        // pair p's slabs ready
        __syncthreads();

        // prefetch pair p+1 (k=2p+2, 2p+3) into slabs (k%4); overlaps compute
        {
            int ka = k0 + 2, kb = k0 + 3;
            if (ka < nu) {
                const uint4* gb = g_B4 + (ub + ka) * 2176;
                uint32_t dst = sb + B_OFF + (uint32_t)(ka & 3) * BBUF;
                for (int kk = tid; kk < 2176; kk += 256) cp16(dst + kk * 16, gb + kk);
            }
            if (kb < nu) {
                const uint4* gb = g_B4 + (ub + kb) * 2176;
                uint32_t dst = sb + B_OFF + (uint32_t)(kb & 3) * BBUF;
                for (int kk = tid; kk < 2176; kk += 256) cp16(dst + kk * 16, gb + kk);
            }
            CP_COMMIT();
        }

        const uint32_t b0Base = sb + B_OFF + (uint32_t)(k0 & 3) * BBUF + bOff;
        const uint32_t b1Base = sb + B_OFF + (uint32_t)((k0 + 1) & 3) * BBUF + bOff;

        float accP0[4][4][4], accP1[4][4][4];
#pragma unroll
        for (int mt = 0; mt < 4; ++mt)
#pragma unroll
            for (int nt = 0; nt < 4; ++nt)
#pragma unroll
                for (int q = 0; q < 4; ++q) { accP0[mt][nt][q] = 0.0f; accP1[mt][nt][q] = 0.0f; }

#pragma unroll
        for (int kc = 0; kc < 8; ++kc) {
            uint32_t af[4][4], bf0[2][4], bf1[2][4];
#pragma unroll
            for (int mt = 0; mt < 4; ++mt)
                LDSM4(af[mt], sb + TH_OFF + aOff
                              + (uint32_t)mt * 16 * (LDA * 2) + (uint32_t)kc * 32);
#pragma unroll
            for (int bt = 0; bt < 2; ++bt) {
                LDSM4(bf0[bt], b0Base + (uint32_t)bt * 16 * (LDA * 2) + (uint32_t)kc * 32);
                LDSM4(bf1[bt], b1Base + (uint32_t)bt * 16 * (LDA * 2) + (uint32_t)kc * 32);
            }
#pragma unroll
            for (int mt = 0; mt < 4; ++mt)
#pragma unroll
                for (int nt = 0; nt < 4; ++nt) {
                    MMA(accP0[mt][nt], af[mt],
                        bf0[nt >> 1][(nt & 1) * 2], bf0[nt >> 1][(nt & 1) * 2 + 1]);
                    MMA(accP1[mt][nt], af[mt],
                        bf1[nt >> 1][(nt & 1) * 2], bf1[nt >> 1][(nt & 1) * 2 + 1]);
                }
        }

        // C += h[.,k0]*P0 + h[.,k0+1]*P1   (fp32)
        const float* hrow0 = hbase + k0 * 128;
        const float* hrow1 = hrow0 + 128;
#pragma unroll
        for (int mt = 0; mt < 4; ++mt) {
            int r = m0w + mt * 16 + (l >> 2);
            float h01 = hrow0[r], h02 = hrow0[r + 8];
            float h11 = hrow1[r], h12 = hrow1[r + 8];
#pragma unroll
            for (int nt = 0; nt < 4; ++nt) {
                accC[mt][nt][0] += h01 * accP0[mt][nt][0] + h11 * accP1[mt][nt][0];
                accC[mt][nt][1] += h01 * accP0[mt][nt][1] + h11 * accP1[mt][nt][1];
                accC[mt][nt][2] += h02 * accP0[mt][nt][2] + h12 * accP1[mt][nt][2];
                accC[mt][nt][3] += h02 * accP0[mt][nt][3] + h12 * accP1[mt][nt][3];
            }
        }
    }

    if (tail) {            // last odd u (k = nu-1)
        const int k0 = nu - 1;
        CP_WAIT0();
        __syncthreads();
        const uint32_t b0Base = sb + B_OFF + (uint32_t)(k0 & 3) * BBUF + bOff;

        float accP0[4][4][4];
#pragma unroll
        for (int mt = 0; mt < 4; ++mt)
#pragma unroll
            for (int nt = 0; nt < 4; ++nt)
#pragma unroll
                for (int q = 0; q < 4; ++q) accP0[mt][nt][q] = 0.0f;

#pragma unroll
        for (int kc = 0; kc < 8; ++kc) {
            uint32_t af[4][4], bf0[2][4];
#pragma unroll
            for (int mt = 0; mt < 4; ++mt)
                LDSM4(af[mt], sb + TH_OFF + aOff
                              + (uint32_t)mt * 16 * (LDA * 2) + (uint32_t)kc * 32);
#pragma unroll
            for (int bt = 0; bt < 2; ++bt)
                LDSM4(bf0[bt], b0Base + (uint32_t)bt * 16 * (LDA * 2) + (uint32_t)kc * 32);
#pragma unroll
            for (int mt = 0; mt < 4; ++mt)
#pragma unroll
                for (int nt = 0; nt < 4; ++nt)
                    MMA(accP0[mt][nt], af[mt],
                        bf0[nt >> 1][(nt & 1) * 2], bf0[nt >> 1][(nt & 1) * 2 + 1]);
        }
        const float* hrow0 = hbase + k0 * 128;
#pragma unroll
        for (int mt = 0; mt < 4; ++mt) {
            int r = m0w + mt * 16 + (l >> 2);
            float h01 = hrow0[r], h02 = hrow0[r + 8];
#pragma unroll
            for (int nt = 0; nt < 4; ++nt) {
                accC[mt][nt][0] += h01 * accP0[mt][nt][0];
                accC[mt][nt][1] += h01 * accP0[mt][nt][1];
                accC[mt][nt][2] += h02 * accP0[mt][nt][2];
                accC[mt][nt][3] += h02 * accP0[mt][nt][3];
            }
        }
    }

    // epilogue: cutoff mask + scatter-add
#pragma unroll
    for (int mt = 0; mt < 4; ++mt) {
        int e1 = e0 + m0w + mt * 16 + (l >> 2);
        int e2 = e1 + 8;
        float d1 = dist[e1], d2 = dist[e2];
        bool ok1 = (d1 <= 8.0f), ok2 = (d2 <= 8.0f);
        float* r1 = g_msg + (long long)eidx[N_EDGES + e1] * UNITS;
        float* r2 = g_msg + (long long)eidx[N_EDGES + e2] * UNITS;
#pragma unroll
        for (int nt = 0; nt < 4; ++nt) {
            int n = n0w + nt * 8 + (l & 3) * 2;
            if (ok1) {
                atomicAdd(r1 + n,     accC[mt][nt][0]);
                atomicAdd(r1 + n + 1, accC[mt][nt][1]);
            }
            if (ok2) {
                atomicAdd(r2 + n,     accC[mt][nt][2]);
                atomicAdd(r2 + n + 1, accC[mt][nt][3]);
            }
        }
    }
}

// ---------------------------------------------------------------------------
// kernel 4: out = silu(messages), float4
// ---------------------------------------------------------------------------
__global__ void out_kernel(float* __restrict__ out) {
    int i = blockIdx.x * blockDim.x + threadIdx.x;  // grid sized exactly (160000)
    float4 x = ((const float4*)g_msg)[i];
    float4 y;
    y.x = silu_f(x.x); y.y = silu_f(x.y); y.z = silu_f(x.z); y.w = silu_f(x.w);
    ((float4*)out)[i] = y;
}

// ---------------------------------------------------------------------------
extern "C" void kernel_launch(void* const* d_in, const int* in_sizes, int n_in,
                              void* d_out, int out_size) {
    const float* nf   = (const float*)d_in[0];
    const int*   eidx = (const int*)  d_in[1];
    const float* dist = (const float*)d_in[2];
    const float* W1   = (const float*)d_in[3];
    const float* b1   = (const float*)d_in[4];
    const float* W2   = (const float*)d_in[5];
    const float* b2   = (const float*)d_in[6];
    const float* Wt   = (const float*)d_in[7];
    float* out = (float*)d_out;

    const int PREP_SMEM = (16384 + 6400 + 128 + 64 * 129 + 64 * 51) * 4;
    cudaFuncSetAttribute(prep_kernel, cudaFuncAttributeMaxDynamicSharedMemorySize, PREP_SMEM);
    cudaFuncSetAttribute(conv_kernel, cudaFuncAttributeMaxDynamicSharedMemorySize, CONV_SMEM);

    w2_zero_kernel<<<129 * 2048 / 256, 256>>>(W2, b2);
    prep_kernel<<<N_EDGES / 64, 256, PREP_SMEM>>>(nf, eidx, dist, W1, b1, Wt);
    conv_kernel<<<dim3(N_EDGES / 128, 2), 256, CONV_SMEM>>>(eidx, dist);
    out_kernel<<<(N_NODES * UNITS / 4) / 256, 256>>>(out);
}